// round 4
// baseline (speedup 1.0000x reference)
#include <cuda_runtime.h>
#include <cuda_bf16.h>
#include <cstdint>

#define NB      32
#define NRINGS  10
#define NANG    36
#define NPTS    (NRINGS * NANG)       // 360
#define NTGT    16384
#define NFLAT   (NB * NTGT)           // 524288 flat targets
#define NGRP    (NFLAT / 32)          // 16384 32-target groups
#define NBLK    444                   // 148 SMs x 3, near-equal flat ranges
#define TPB     (NRINGS * 32)         // 320: warp = ring
#define MAXT    1184                  // max targets per block (37 groups)

// Monotone-encoded running max of -d2 per (batch,point). Zero-init = -inf
// sentinel; last block resets to 0 each run so graph replays are clean.
__device__ unsigned int g_keys[NB * NPTS];
__device__ unsigned int g_count;      // block-completion counter (reset by last block)

__device__ __forceinline__ unsigned int enc_f32(float f) {
    unsigned int u = __float_as_uint(f);
    return ((int)u < 0) ? ~u : (u | 0x80000000u);
}
__device__ __forceinline__ float dec_f32(unsigned int k) {
    unsigned int u = ((int)k < 0) ? (k & 0x7FFFFFFFu) : ~k;
    return __uint_as_float(u);
}

// Paired-angle evaluation: P = fma(C,U,Acc); m[a]=min(m[a],fma(S,V,P));
// m[36-a]=min(m[36-a],fma(-S,V,P)).  5 instr / 2 angles, constants as FFMA imms.
#define PAIR(AI, BI, CV, SV)                         \
    { float P = fmaf(CV, U, Acc);                    \
      m[AI] = fminf(m[AI], fmaf( SV, V, P));         \
      m[BI] = fminf(m[BI], fmaf(-SV, V, P)); }

__device__ __forceinline__ void eval36(float* m, float U, float V, float Acc) {
    // axis angles: cos or sin is 0
    m[ 0] = fminf(m[ 0], Acc + U);
    m[18] = fminf(m[18], Acc - U);
    m[ 9] = fminf(m[ 9], Acc + V);
    m[27] = fminf(m[27], Acc - V);
    // 16 cos-sharing pairs (a, 36-a)
    PAIR( 1, 35,  0.9848077530f, 0.1736481777f)
    PAIR( 2, 34,  0.9396926208f, 0.3420201433f)
    PAIR( 3, 33,  0.8660254038f, 0.5f)
    PAIR( 4, 32,  0.7660444431f, 0.6427876097f)
    PAIR( 5, 31,  0.6427876097f, 0.7660444431f)
    PAIR( 6, 30,  0.5f,          0.8660254038f)
    PAIR( 7, 29,  0.3420201433f, 0.9396926208f)
    PAIR( 8, 28,  0.1736481777f, 0.9848077530f)
    PAIR(10, 26, -0.1736481777f, 0.9848077530f)
    PAIR(11, 25, -0.3420201433f, 0.9396926208f)
    PAIR(12, 24, -0.5f,          0.8660254038f)
    PAIR(13, 23, -0.6427876097f, 0.7660444431f)
    PAIR(14, 22, -0.7660444431f, 0.6427876097f)
    PAIR(15, 21, -0.8660254038f, 0.5f)
    PAIR(16, 20, -0.9396926208f, 0.3420201433f)
    PAIR(17, 19, -0.9848077530f, 0.1736481777f)
}

// Process one batch segment [t0, t1) of this block's staged targets for (b, ring),
// then fold the warp minima into g_keys.
__device__ __forceinline__ void process_segment(
    const float4* __restrict__ sm, const float* __restrict__ pred,
    int b, int ring, int lane, int t0, int t1)
{
    const float r  = pred[b * NRINGS + ring];
    const float py = 0.15f * (float)ring - 0.7f;
    const float Kr = fmaf(r, r, fmaf(py, py, 0.0016f));

    const float INF = __int_as_float(0x7f800000);
    float m[NANG];
    #pragma unroll
    for (int a = 0; a < NANG; a++) m[a] = INF;

    #pragma unroll 2
    for (int t = t0 + lane; t < t1; t += 32) {
        float4 v  = sm[t];
        float Acc = fmaf(py, v.y, v.w) + Kr;
        float U   = r * v.x;
        float V   = r * v.z;
        eval36(m, U, V, Acc);
    }

    const unsigned int pbase = (unsigned)(b * NPTS + ring * NANG);
    #pragma unroll
    for (int a = 0; a < NANG; a++) {
        float v = m[a];
        #pragma unroll
        for (int o = 16; o > 0; o >>= 1)
            v = fminf(v, __shfl_xor_sync(0xffffffffu, v, o));
        if (lane == (a & 31))
            atomicMax(&g_keys[pbase + a], enc_f32(-v));
    }
}

__global__ void __launch_bounds__(TPB)
chamfer_fused_kernel(const float* __restrict__ pred,
                     const float* __restrict__ target,
                     float* __restrict__ out)
{
    __shared__ float4 sm[MAXT];
    __shared__ float  wsum[NRINGS];
    __shared__ unsigned int is_last;

    const int bid = blockIdx.x;
    const int tid = threadIdx.x;

    // Flat, 32-aligned, near-equal target range for this block.
    const int g0 = (bid * NGRP) / NBLK;
    const int g1 = ((bid + 1) * NGRP) / NBLK;
    const int s0 = g0 * 32;             // global flat target start
    const int n  = (g1 - g0) * 32;      // targets in this block (1152 or 1184)

    // Stage + preprocess (batch-independent): (2tx-0.08, -2ty, -2tz, t2-0.08tx)
    const float* tg = target + (size_t)s0 * 3;
    for (int i = tid; i < n; i += TPB) {
        float tx = tg[i * 3 + 0];
        float ty = tg[i * 3 + 1];
        float tz = tg[i * 3 + 2];
        float t2 = tx * tx + ty * ty + tz * tz;
        sm[i] = make_float4(2.0f * tx - 0.08f, -2.0f * ty, -2.0f * tz,
                            fmaf(-0.08f, tx, t2));
    }
    __syncthreads();

    const int ring = tid >> 5;
    const int lane = tid & 31;

    // At most one batch boundary inside the block's range.
    const int b0 = s0 >> 14;                           // / 16384
    const int bd = min(n, ((b0 + 1) << 14) - s0);      // local boundary (multiple of 32)

    process_segment(sm, pred, b0, ring, lane, 0, bd);
    if (bd < n)
        process_segment(sm, pred, b0 + 1, ring, lane, bd, n);

    // ---- last-block-done finalize (single launch, no second kernel) ----
    __threadfence();
    if (tid == 0)
        is_last = (atomicAdd(&g_count, 1u) == (unsigned)(NBLK - 1));
    __syncthreads();
    if (!is_last) return;
    __threadfence();

    // Deterministic mean over 11520 decoded keys (46 KB, L2-resident).
    uint4* keys4 = (uint4*)g_keys;
    const int n4 = (NB * NPTS) / 4;     // 2880
    float s = 0.0f;
    for (int i = tid; i < n4; i += TPB) {
        uint4 k = keys4[i];
        s += fmaxf(-dec_f32(k.x), 0.0f);
        s += fmaxf(-dec_f32(k.y), 0.0f);
        s += fmaxf(-dec_f32(k.z), 0.0f);
        s += fmaxf(-dec_f32(k.w), 0.0f);
    }
    #pragma unroll
    for (int o = 16; o > 0; o >>= 1) s += __shfl_down_sync(0xffffffffu, s, o);
    if (lane == 0) wsum[ring] = s;
    __syncthreads();
    if (tid == 0) {
        float tot = 0.0f;
        #pragma unroll
        for (int w = 0; w < NRINGS; w++) tot += wsum[w];
        out[0] = tot / (float)(NB * NPTS);
    }
    __syncthreads();   // all reads of g_keys complete before reset

    // Reset sentinel state for the next graph replay.
    const uint4 z4 = make_uint4(0u, 0u, 0u, 0u);
    for (int i = tid; i < n4; i += TPB) keys4[i] = z4;
    if (tid == 0) g_count = 0u;
}

extern "C" void kernel_launch(void* const* d_in, const int* in_sizes, int n_in,
                              void* d_out, int out_size) {
    const float* pred   = (const float*)d_in[0];   // (32, 10)
    const float* target = (const float*)d_in[1];   // (32, 16384, 3)
    float* out = (float*)d_out;

    chamfer_fused_kernel<<<NBLK, TPB>>>(pred, target, out);
}